// round 7
// baseline (speedup 1.0000x reference)
#include <cuda_runtime.h>
#include <cuda_bf16.h>
#include <math.h>
#include <cstdint>

// ---------------------------------------------------------------------------
// SpectroTFDecoder: pre-LN transformer decoder layer, fp32 I/O.
// GEMMs: mma.sync bf16 tensor cores, hi/lo split (3-MMA compensation),
// cp.async 3-stage pipeline. Attention/LN SIMT fp32; splits fused into
// producers (LN / attention / FF1 epilogues).
// Input order: 0 x, 1 src_x, 2 mask, 3 src_mask, 4-9 ln{1,2,3}_{g,b},
// 10-17 weights (sa_wq,sa_wk,sa_wv,sa_wo,ca_wq,ca_wk,ca_wv,ca_wo),
// 18-25 biases (same order), 26-29 ff_w1,ff_b1,ff_w2,ff_b2.
// ---------------------------------------------------------------------------

#define D_MODEL 1024
#define BATCH   4
#define TSEQ    1024
#define N_ROWS  (BATCH * TSEQ)
#define NHEAD   16
#define DHEAD   64
#define DFF_    4096
#define LN_EPS  1e-6f

// fp32 scratch
__device__ float g_q  [N_ROWS * D_MODEL];
__device__ float g_k  [N_ROWS * D_MODEL];
__device__ float g_v  [N_ROWS * D_MODEL];
__device__ float g_x1 [N_ROWS * D_MODEL];
__device__ float g_x2 [N_ROWS * D_MODEL];

// bf16 hi/lo scratch
#define WQ_OFF  0
#define WK_OFF  (1 << 20)
#define WV_OFF  (2 << 20)
#define WO_OFF  (3 << 20)
#define CQ_OFF  (4 << 20)
#define CK_OFF  (5 << 20)
#define CV_OFF  (6 << 20)
#define CO_OFF  (7 << 20)
#define W1_OFF  (8 << 20)
#define W2_OFF  (12 << 20)
__device__ __nv_bfloat16 g_whi[16 << 20];   // weights (transposed [N,K])
__device__ __nv_bfloat16 g_wlo[16 << 20];
__device__ __nv_bfloat16 g_ahi[4 << 20];    // activation split (D-wide)
__device__ __nv_bfloat16 g_alo[4 << 20];
__device__ __nv_bfloat16 g_shi[4 << 20];    // src_x split (persistent)
__device__ __nv_bfloat16 g_slo[4 << 20];
__device__ __nv_bfloat16 g_fhi[16 << 20];   // FF intermediate split
__device__ __nv_bfloat16 g_flo[16 << 20];

// ---------------------------------------------------------------------------
// asm helpers
// ---------------------------------------------------------------------------
__device__ __forceinline__ uint32_t smem_u32(const void* p) {
    uint32_t a;
    asm("{ .reg .u64 t; cvta.to.shared.u64 t, %1; cvt.u32.u64 %0, t; }"
        : "=r"(a) : "l"(p));
    return a;
}
__device__ __forceinline__ void ldm4(uint32_t* r, uint32_t a) {
    asm volatile("ldmatrix.sync.aligned.m8n8.x4.shared.b16 {%0,%1,%2,%3}, [%4];"
                 : "=r"(r[0]), "=r"(r[1]), "=r"(r[2]), "=r"(r[3]) : "r"(a));
}
__device__ __forceinline__ void mma16816(float* c, const uint32_t* a,
                                         const uint32_t* b) {
    asm volatile(
        "mma.sync.aligned.m16n8k16.row.col.f32.bf16.bf16.f32 "
        "{%0,%1,%2,%3},{%4,%5,%6,%7},{%8,%9},{%0,%1,%2,%3};"
        : "+f"(c[0]), "+f"(c[1]), "+f"(c[2]), "+f"(c[3])
        : "r"(a[0]), "r"(a[1]), "r"(a[2]), "r"(a[3]), "r"(b[0]), "r"(b[1]));
}
#define CPA16(dst, src) \
    asm volatile("cp.async.cg.shared.global [%0], [%1], 16;" :: "r"(dst), "l"(src))
#define CPA_COMMIT() asm volatile("cp.async.commit_group;" ::: "memory")
#define CPA_WAIT1()  asm volatile("cp.async.wait_group 1;"  ::: "memory")

__device__ __forceinline__ void split1(float a, __nv_bfloat16& h, __nv_bfloat16& l) {
    h = __float2bfloat16(a);
    l = __float2bfloat16(a - __bfloat162float(h));
}

// ---------------------------------------------------------------------------
// split: fp32 -> bf16 hi + lo. n multiple of 1024.
// ---------------------------------------------------------------------------
__global__ __launch_bounds__(256)
void split_kernel(const float* __restrict__ in, __nv_bfloat16* __restrict__ hi,
                  __nv_bfloat16* __restrict__ lo)
{
    const int i = (blockIdx.x * 256 + threadIdx.x) * 4;
    float4 a = *(const float4*)(in + i);
    float av[4] = {a.x, a.y, a.z, a.w};
    __nv_bfloat16 hv[4], lv[4];
    #pragma unroll
    for (int j = 0; j < 4; j++) split1(av[j], hv[j], lv[j]);
    __nv_bfloat162 h01{hv[0], hv[1]}, h23{hv[2], hv[3]};
    __nv_bfloat162 l01{lv[0], lv[1]}, l23{lv[2], lv[3]};
    *(__nv_bfloat162*)(hi + i)     = h01;
    *(__nv_bfloat162*)(hi + i + 2) = h23;
    *(__nv_bfloat162*)(lo + i)     = l01;
    *(__nv_bfloat162*)(lo + i + 2) = l23;
}

// ---------------------------------------------------------------------------
// transpose + split: W[K,N] fp32 -> out[N,K] bf16 hi/lo.
// ---------------------------------------------------------------------------
__global__ __launch_bounds__(256)
void tsplit_kernel(const float* __restrict__ W, __nv_bfloat16* __restrict__ hi,
                   __nv_bfloat16* __restrict__ lo, int K, int N)
{
    __shared__ float t[32][33];
    const int x = threadIdx.x & 31;
    const int y = threadIdx.x >> 5;
    const int k0 = blockIdx.y * 32;
    const int n0 = blockIdx.x * 32;
    #pragma unroll
    for (int r = y; r < 32; r += 8)
        t[r][x] = W[(size_t)(k0 + r) * N + n0 + x];
    __syncthreads();
    #pragma unroll
    for (int r = y; r < 32; r += 8) {
        float a = t[x][r];
        __nv_bfloat16 h, l;
        split1(a, h, l);
        const size_t o = (size_t)(n0 + r) * K + k0 + x;
        hi[o] = h;
        lo[o] = l;
    }
}

// ---------------------------------------------------------------------------
// LayerNorm fused with hi/lo split output.
// ---------------------------------------------------------------------------
__global__ __launch_bounds__(256)
void ln_split_kernel(const float* __restrict__ x, const float* __restrict__ g,
                     const float* __restrict__ bta,
                     __nv_bfloat16* __restrict__ hi, __nv_bfloat16* __restrict__ lo)
{
    const int row = blockIdx.x;
    const int t = threadIdx.x;
    const float* xr = x + (size_t)row * D_MODEL;
    float4 xv = *(const float4*)(xr + t * 4);

    float s = xv.x + xv.y + xv.z + xv.w;
    __shared__ float red[8];
    #pragma unroll
    for (int off = 16; off > 0; off >>= 1) s += __shfl_xor_sync(~0u, s, off);
    if ((t & 31) == 0) red[t >> 5] = s;
    __syncthreads();
    float tot = 0.f;
    #pragma unroll
    for (int i = 0; i < 8; i++) tot += red[i];
    const float mu = tot * (1.f / 1024.f);

    const float dx0 = xv.x - mu, dx1 = xv.y - mu, dx2 = xv.z - mu, dx3 = xv.w - mu;
    float sq = dx0*dx0 + dx1*dx1 + dx2*dx2 + dx3*dx3;
    #pragma unroll
    for (int off = 16; off > 0; off >>= 1) sq += __shfl_xor_sync(~0u, sq, off);
    __syncthreads();
    if ((t & 31) == 0) red[t >> 5] = sq;
    __syncthreads();
    float tot2 = 0.f;
    #pragma unroll
    for (int i = 0; i < 8; i++) tot2 += red[i];
    const float sigma = sqrtf(tot2 * (1.f / 1024.f));
    const float inv = 1.f / (sigma + LN_EPS);

    float4 gv = *(const float4*)(g + t * 4);
    float4 bv = *(const float4*)(bta + t * 4);
    float o0 = dx0 * inv * gv.x + bv.x;
    float o1 = dx1 * inv * gv.y + bv.y;
    float o2 = dx2 * inv * gv.z + bv.z;
    float o3 = dx3 * inv * gv.w + bv.w;

    __nv_bfloat16 h0,h1,h2,h3,l0,l1,l2,l3;
    split1(o0,h0,l0); split1(o1,h1,l1); split1(o2,h2,l2); split1(o3,h3,l3);
    const size_t o = (size_t)row * D_MODEL + t * 4;
    __nv_bfloat162 ha{h0,h1}, hb{h2,h3}, la{l0,l1}, lb{l2,l3};
    *(__nv_bfloat162*)(hi + o)     = ha;
    *(__nv_bfloat162*)(hi + o + 2) = hb;
    *(__nv_bfloat162*)(lo + o)     = la;
    *(__nv_bfloat162*)(lo + o + 2) = lb;
}

// ---------------------------------------------------------------------------
// Tensor-core GEMM with cp.async 3-stage pipeline.
// C[M,N] = A@W + bias (+res), optional ReLU, optional split-bf16 output.
// A split [M,K], B = W^T split [N,K]. BM=BN=128, BK=32, 8 warps (2x4),
// warp tile 64x32, 3-MMA hi/lo compensation, fp32 accum.
// ---------------------------------------------------------------------------
#define TGA_ROW 40                       // padded row stride (bf16 elems)
#define TGA_BYT (128 * TGA_ROW * 2)      // 10240 B per tile
#define TG_STAGE (4 * TGA_BYT)           // 40960 B per stage
#define TC_SMEM (3 * TG_STAGE)           // 122880 B

template<bool RELU, bool RES, bool SPLITOUT>
__global__ __launch_bounds__(256, 1)
void tc_gemm(const __nv_bfloat16* __restrict__ Ahi, const __nv_bfloat16* __restrict__ Alo,
             const __nv_bfloat16* __restrict__ Bhi, const __nv_bfloat16* __restrict__ Blo,
             const float* __restrict__ bias, const float* __restrict__ res,
             float* __restrict__ C,
             __nv_bfloat16* __restrict__ Chi, __nv_bfloat16* __restrict__ Clo,
             int M, int N, int K)
{
    extern __shared__ __align__(128) char dynsmem[];
    const uint32_t sb = smem_u32(dynsmem);
    const int tid = threadIdx.x;
    const int lane = tid & 31;
    const int wid = tid >> 5;
    const int wm = wid >> 2;
    const int wn = wid & 3;
    const int bm = blockIdx.y * 128;
    const int bn = blockIdx.x * 128;

    // staging mapping: thread -> (row 0..127, 16-elem half)
    const int srow = tid >> 1;
    const int shalf = (tid & 1) * 16;
    const uint32_t so = (uint32_t)(srow * TGA_ROW + shalf) * 2;

    const char* gAh = (const char*)(Ahi + (size_t)(bm + srow) * K + shalf);
    const char* gAl = (const char*)(Alo + (size_t)(bm + srow) * K + shalf);
    const char* gBh = (const char*)(Bhi + (size_t)(bn + srow) * K + shalf);
    const char* gBl = (const char*)(Blo + (size_t)(bn + srow) * K + shalf);

    // ldmatrix offsets within a stage
    const uint32_t a_off = (uint32_t)((lane & 15) * TGA_ROW * 2 + (lane >> 4) * 16);
    const uint32_t b_off = (uint32_t)((((lane >> 4) << 3) + (lane & 7)) * TGA_ROW * 2
                                      + ((lane >> 3) & 1) * 16);
    uint32_t aAddr[4], bAddr[2];
    #pragma unroll
    for (int mt = 0; mt < 4; mt++)
        aAddr[mt] = sb + (uint32_t)((wm * 64 + mt * 16) * TGA_ROW * 2) + a_off;
    #pragma unroll
    for (int ng = 0; ng < 2; ng++)
        bAddr[ng] = sb + 2 * TGA_BYT + (uint32_t)((wn * 32 + ng * 16) * TGA_ROW * 2) + b_off;

    float acc[4][4][4];
    #pragma unroll
    for (int mt = 0; mt < 4; mt++)
        #pragma unroll
        for (int nt = 0; nt < 4; nt++)
            #pragma unroll
            for (int r = 0; r < 4; r++) acc[mt][nt][r] = 0.f;

    const int nk = K >> 5;     // BK = 32

    // cp.async stage issue
    auto issue = [&](int s, int kt) {
        const uint32_t tb = sb + (uint32_t)s * TG_STAGE;
        const int gb = kt * 64;     // 32 elems * 2B
        CPA16(tb + so,                   gAh + gb);
        CPA16(tb + so + 16,              gAh + gb + 16);
        CPA16(tb + TGA_BYT + so,         gAl + gb);
        CPA16(tb + TGA_BYT + so + 16,    gAl + gb + 16);
        CPA16(tb + 2*TGA_BYT + so,       gBh + gb);
        CPA16(tb + 2*TGA_BYT + so + 16,  gBh + gb + 16);
        CPA16(tb + 3*TGA_BYT + so,       gBl + gb);
        CPA16(tb + 3*TGA_BYT + so + 16,  gBl + gb + 16);
    };

    issue(0, 0); CPA_COMMIT();
    issue(1, 1); CPA_COMMIT();

    int cs = 0;   // compute stage
    for (int kt = 0; kt < nk; kt++) {
        CPA_WAIT1();
        __syncthreads();
        if (kt + 2 < nk) {
            int is = cs + 2; if (is >= 3) is -= 3;
            issue(is, kt + 2);
        }
        CPA_COMMIT();

        const uint32_t stg = (uint32_t)cs * TG_STAGE;
        #pragma unroll
        for (int ks = 0; ks < 2; ks++) {
            const uint32_t kb = stg + ks * 32;
            uint32_t ah[4][4], al[4][4], bh[2][4], bl[2][4];
            #pragma unroll
            for (int mt = 0; mt < 4; mt++) {
                ldm4(ah[mt], aAddr[mt] + kb);
                ldm4(al[mt], aAddr[mt] + TGA_BYT + kb);
            }
            #pragma unroll
            for (int ng = 0; ng < 2; ng++) {
                ldm4(bh[ng], bAddr[ng] + kb);
                ldm4(bl[ng], bAddr[ng] + TGA_BYT + kb);
            }
            #pragma unroll
            for (int mt = 0; mt < 4; mt++) {
                #pragma unroll
                for (int nt = 0; nt < 4; nt++) {
                    const int ng = nt >> 1;
                    const int hf = (nt & 1) * 2;
                    mma16816(acc[mt][nt], ah[mt], &bh[ng][hf]);
                    mma16816(acc[mt][nt], ah[mt], &bl[ng][hf]);
                    mma16816(acc[mt][nt], al[mt], &bh[ng][hf]);
                }
            }
        }
        cs++; if (cs == 3) cs = 0;
    }

    // epilogue
    const int er = lane >> 2;
    const int ec = (lane & 3) * 2;
    #pragma unroll
    for (int mt = 0; mt < 4; mt++) {
        const int row0 = bm + wm * 64 + mt * 16 + er;
        #pragma unroll
        for (int nt = 0; nt < 4; nt++) {
            const int col = bn + wn * 32 + nt * 8 + ec;
            float2 bv = *(const float2*)(bias + col);
            float v0 = acc[mt][nt][0] + bv.x;
            float v1 = acc[mt][nt][1] + bv.y;
            float v2 = acc[mt][nt][2] + bv.x;
            float v3 = acc[mt][nt][3] + bv.y;
            if (RELU) {
                v0 = fmaxf(v0, 0.f); v1 = fmaxf(v1, 0.f);
                v2 = fmaxf(v2, 0.f); v3 = fmaxf(v3, 0.f);
            }
            if (RES) {
                float2 r0 = *(const float2*)(res + (size_t)row0 * N + col);
                float2 r1 = *(const float2*)(res + (size_t)(row0 + 8) * N + col);
                v0 += r0.x; v1 += r0.y; v2 += r1.x; v3 += r1.y;
            }
            if (SPLITOUT) {
                __nv_bfloat16 h0,h1,h2,h3,l0,l1,l2,l3;
                split1(v0,h0,l0); split1(v1,h1,l1);
                split1(v2,h2,l2); split1(v3,h3,l3);
                __nv_bfloat162 ha{h0,h1}, hb{h2,h3}, la{l0,l1}, lb{l2,l3};
                *(__nv_bfloat162*)(Chi + (size_t)row0 * N + col)       = ha;
                *(__nv_bfloat162*)(Chi + (size_t)(row0 + 8) * N + col) = hb;
                *(__nv_bfloat162*)(Clo + (size_t)row0 * N + col)       = la;
                *(__nv_bfloat162*)(Clo + (size_t)(row0 + 8) * N + col) = lb;
            } else {
                float2 o0 = {v0, v1};
                float2 o1 = {v2, v3};
                *(float2*)(C + (size_t)row0 * N + col) = o0;
                *(float2*)(C + (size_t)(row0 + 8) * N + col) = o1;
            }
        }
    }
}

// ---------------------------------------------------------------------------
// Flash attention (register-tiled), epilogue writes bf16 hi/lo split.
// ---------------------------------------------------------------------------
#define AST 68
#define ATTN_SMEM (4 * 64 * AST * (int)sizeof(float))

__global__ __launch_bounds__(256)
void attn_kernel(const float* __restrict__ Q, const float* __restrict__ Kv,
                 const float* __restrict__ Vv,
                 __nv_bfloat16* __restrict__ Ohi, __nv_bfloat16* __restrict__ Olo,
                 int causal)
{
    const int qt = blockIdx.x;
    const int h  = blockIdx.y;
    const int b  = blockIdx.z;
    const int tid = threadIdx.x;
    const int ty = tid >> 4;
    const int tx = tid & 15;

    const size_t base = ((size_t)b * TSEQ) * D_MODEL + (size_t)h * DHEAD;

    extern __shared__ __align__(128) char dynsmem[];
    float* sm = (float*)dynsmem;
    float* Qt = sm;
    float* Kt = sm + 64 * AST;
    float* Vs = sm + 2 * 64 * AST;
    float* Pt = sm + 3 * 64 * AST;

    const int r  = tid >> 2;
    const int cc = (tid & 3) * 16;

    {
        const float* src = Q + base + (size_t)(qt * 64 + r) * D_MODEL + cc;
        #pragma unroll
        for (int c = 0; c < 16; c += 4) {
            float4 v4 = *(const float4*)(src + c);
            Qt[(cc + c + 0) * AST + r] = v4.x * 0.125f;
            Qt[(cc + c + 1) * AST + r] = v4.y * 0.125f;
            Qt[(cc + c + 2) * AST + r] = v4.z * 0.125f;
            Qt[(cc + c + 3) * AST + r] = v4.w * 0.125f;
        }
    }

    float m[4], l[4], acc[4][4];
    #pragma unroll
    for (int i = 0; i < 4; i++) {
        m[i] = -INFINITY; l[i] = 0.f;
        #pragma unroll
        for (int j = 0; j < 4; j++) acc[i][j] = 0.f;
    }

    const int ktEnd = causal ? qt : (TSEQ / 64 - 1);

    for (int kt = 0; kt <= ktEnd; kt++) {
        __syncthreads();
        {
            const float* ks = Kv + base + (size_t)(kt * 64 + r) * D_MODEL + cc;
            const float* vs = Vv + base + (size_t)(kt * 64 + r) * D_MODEL + cc;
            #pragma unroll
            for (int c = 0; c < 16; c += 4) {
                float4 k4 = *(const float4*)(ks + c);
                Kt[(cc + c + 0) * AST + r] = k4.x;
                Kt[(cc + c + 1) * AST + r] = k4.y;
                Kt[(cc + c + 2) * AST + r] = k4.z;
                Kt[(cc + c + 3) * AST + r] = k4.w;
                float4 v4 = *(const float4*)(vs + c);
                *(float4*)&Vs[r * AST + cc + c] = v4;
            }
        }
        __syncthreads();

        float s[4][4];
        #pragma unroll
        for (int i = 0; i < 4; i++)
            #pragma unroll
            for (int j = 0; j < 4; j++) s[i][j] = 0.f;
        #pragma unroll 4
        for (int dd = 0; dd < 64; dd++) {
            float4 q4 = *(const float4*)&Qt[dd * AST + 4 * ty];
            float4 k4 = *(const float4*)&Kt[dd * AST + 4 * tx];
            float qa[4] = {q4.x, q4.y, q4.z, q4.w};
            float ka[4] = {k4.x, k4.y, k4.z, k4.w};
            #pragma unroll
            for (int i = 0; i < 4; i++)
                #pragma unroll
                for (int j = 0; j < 4; j++)
                    s[i][j] += qa[i] * ka[j];
        }

        const bool diag = causal && (kt == qt);
        float p[4][4];
        #pragma unroll
        for (int i = 0; i < 4; i++) {
            const int qg = qt * 64 + 4 * ty + i;
            float rmax = -INFINITY;
            #pragma unroll
            for (int j = 0; j < 4; j++) {
                if (diag && (kt * 64 + 4 * tx + j) > qg) s[i][j] = -INFINITY;
                rmax = fmaxf(rmax, s[i][j]);
            }
            rmax = fmaxf(rmax, __shfl_xor_sync(~0u, rmax, 1));
            rmax = fmaxf(rmax, __shfl_xor_sync(~0u, rmax, 2));
            rmax = fmaxf(rmax, __shfl_xor_sync(~0u, rmax, 4));
            rmax = fmaxf(rmax, __shfl_xor_sync(~0u, rmax, 8));
            const float mnew = fmaxf(m[i], rmax);
            const float corr = __expf(m[i] - mnew);
            float rsum = 0.f;
            #pragma unroll
            for (int j = 0; j < 4; j++) {
                p[i][j] = __expf(s[i][j] - mnew);
                rsum += p[i][j];
            }
            rsum += __shfl_xor_sync(~0u, rsum, 1);
            rsum += __shfl_xor_sync(~0u, rsum, 2);
            rsum += __shfl_xor_sync(~0u, rsum, 4);
            rsum += __shfl_xor_sync(~0u, rsum, 8);
            l[i] = l[i] * corr + rsum;
            m[i] = mnew;
            #pragma unroll
            for (int j = 0; j < 4; j++) acc[i][j] *= corr;
        }

        #pragma unroll
        for (int j = 0; j < 4; j++) {
            float4 pj = {p[0][j], p[1][j], p[2][j], p[3][j]};
            *(float4*)&Pt[(4 * tx + j) * AST + 4 * ty] = pj;
        }
        __syncthreads();

        #pragma unroll 4
        for (int kk = 0; kk < 64; kk++) {
            float4 p4 = *(const float4*)&Pt[kk * AST + 4 * ty];
            float4 v4 = *(const float4*)&Vs[kk * AST + 4 * tx];
            float pa[4] = {p4.x, p4.y, p4.z, p4.w};
            float va[4] = {v4.x, v4.y, v4.z, v4.w};
            #pragma unroll
            for (int i = 0; i < 4; i++)
                #pragma unroll
                for (int j = 0; j < 4; j++)
                    acc[i][j] += pa[i] * va[j];
        }
    }

    #pragma unroll
    for (int i = 0; i < 4; i++) {
        const float inv = 1.f / l[i];
        const size_t o = base + (size_t)(qt * 64 + 4 * ty + i) * D_MODEL + 4 * tx;
        float o0 = acc[i][0] * inv, o1 = acc[i][1] * inv;
        float o2 = acc[i][2] * inv, o3 = acc[i][3] * inv;
        __nv_bfloat16 h0,h1,h2,h3,l0,l1,l2,l3;
        split1(o0,h0,l0); split1(o1,h1,l1); split1(o2,h2,l2); split1(o3,h3,l3);
        __nv_bfloat162 ha{h0,h1}, hb{h2,h3}, la{l0,l1}, lb{l2,l3};
        *(__nv_bfloat162*)(Ohi + o)     = ha;
        *(__nv_bfloat162*)(Ohi + o + 2) = hb;
        *(__nv_bfloat162*)(Olo + o)     = la;
        *(__nv_bfloat162*)(Olo + o + 2) = lb;
    }
}

// ---------------------------------------------------------------------------
// Host orchestration
// ---------------------------------------------------------------------------
extern "C" void kernel_launch(void* const* d_in, const int* in_sizes, int n_in,
                              void* d_out, int out_size)
{
    (void)in_sizes; (void)n_in; (void)out_size;
    const float* x     = (const float*)d_in[0];
    const float* src_x = (const float*)d_in[1];
    const float* ln1_g = (const float*)d_in[4];
    const float* ln1_b = (const float*)d_in[5];
    const float* ln2_g = (const float*)d_in[6];
    const float* ln2_b = (const float*)d_in[7];
    const float* ln3_g = (const float*)d_in[8];
    const float* ln3_b = (const float*)d_in[9];
    const float* W[8];
    for (int i = 0; i < 8; i++) W[i] = (const float*)d_in[10 + i];
    const float* Bv[8];
    for (int i = 0; i < 8; i++) Bv[i] = (const float*)d_in[18 + i];
    const float* ff_w1 = (const float*)d_in[26];
    const float* ff_b1 = (const float*)d_in[27];
    const float* ff_w2 = (const float*)d_in[28];
    const float* ff_b2 = (const float*)d_in[29];
    float* out = (float*)d_out;

    float *q, *k, *v, *x1, *x2;
    cudaGetSymbolAddress((void**)&q,  g_q);
    cudaGetSymbolAddress((void**)&k,  g_k);
    cudaGetSymbolAddress((void**)&v,  g_v);
    cudaGetSymbolAddress((void**)&x1, g_x1);
    cudaGetSymbolAddress((void**)&x2, g_x2);
    __nv_bfloat16 *whi, *wlo, *ahi, *alo, *shi, *slo, *fhi, *flo;
    cudaGetSymbolAddress((void**)&whi, g_whi);
    cudaGetSymbolAddress((void**)&wlo, g_wlo);
    cudaGetSymbolAddress((void**)&ahi, g_ahi);
    cudaGetSymbolAddress((void**)&alo, g_alo);
    cudaGetSymbolAddress((void**)&shi, g_shi);
    cudaGetSymbolAddress((void**)&slo, g_slo);
    cudaGetSymbolAddress((void**)&fhi, g_fhi);
    cudaGetSymbolAddress((void**)&flo, g_flo);

    cudaFuncSetAttribute(attn_kernel,
                         cudaFuncAttributeMaxDynamicSharedMemorySize, ATTN_SMEM);
    cudaFuncSetAttribute(tc_gemm<false, false, false>,
                         cudaFuncAttributeMaxDynamicSharedMemorySize, TC_SMEM);
    cudaFuncSetAttribute(tc_gemm<false, true, false>,
                         cudaFuncAttributeMaxDynamicSharedMemorySize, TC_SMEM);
    cudaFuncSetAttribute(tc_gemm<true, false, true>,
                         cudaFuncAttributeMaxDynamicSharedMemorySize, TC_SMEM);

    const dim3 gD (D_MODEL / 128, N_ROWS / 128);   // (8, 32)
    const dim3 gF1(DFF_   / 128, N_ROWS / 128);    // (32, 32)
    const dim3 gAtt(TSEQ / 64, NHEAD, BATCH);
    const dim3 gsq(D_MODEL / 32, D_MODEL / 32);

    // ---- launches 0-4: sa weight prep + ln1 (puts tc_gemm Q at ncu idx 5) ----
    tsplit_kernel<<<gsq, 256>>>(W[0], whi + WQ_OFF, wlo + WQ_OFF, D_MODEL, D_MODEL);
    tsplit_kernel<<<gsq, 256>>>(W[1], whi + WK_OFF, wlo + WK_OFF, D_MODEL, D_MODEL);
    tsplit_kernel<<<gsq, 256>>>(W[2], whi + WV_OFF, wlo + WV_OFF, D_MODEL, D_MODEL);
    tsplit_kernel<<<gsq, 256>>>(W[3], whi + WO_OFF, wlo + WO_OFF, D_MODEL, D_MODEL);
    ln_split_kernel<<<N_ROWS, 256>>>(x, ln1_g, ln1_b, ahi, alo);

    // ---- self-attention block ----
    tc_gemm<false, false, false><<<gD, 256, TC_SMEM>>>(ahi, alo, whi + WQ_OFF, wlo + WQ_OFF, Bv[0], nullptr, q, nullptr, nullptr, N_ROWS, D_MODEL, D_MODEL);
    tc_gemm<false, false, false><<<gD, 256, TC_SMEM>>>(ahi, alo, whi + WK_OFF, wlo + WK_OFF, Bv[1], nullptr, k, nullptr, nullptr, N_ROWS, D_MODEL, D_MODEL);
    tc_gemm<false, false, false><<<gD, 256, TC_SMEM>>>(ahi, alo, whi + WV_OFF, wlo + WV_OFF, Bv[2], nullptr, v, nullptr, nullptr, N_ROWS, D_MODEL, D_MODEL);
    attn_kernel<<<gAtt, 256, ATTN_SMEM>>>(q, k, v, ahi, alo, 1);
    tc_gemm<false, true, false><<<gD, 256, TC_SMEM>>>(ahi, alo, whi + WO_OFF, wlo + WO_OFF, Bv[3], x, x1, nullptr, nullptr, N_ROWS, D_MODEL, D_MODEL);

    // ---- cross-attention block ----
    tsplit_kernel<<<gsq, 256>>>(W[4], whi + CQ_OFF, wlo + CQ_OFF, D_MODEL, D_MODEL);
    tsplit_kernel<<<gsq, 256>>>(W[5], whi + CK_OFF, wlo + CK_OFF, D_MODEL, D_MODEL);
    tsplit_kernel<<<gsq, 256>>>(W[6], whi + CV_OFF, wlo + CV_OFF, D_MODEL, D_MODEL);
    tsplit_kernel<<<gsq, 256>>>(W[7], whi + CO_OFF, wlo + CO_OFF, D_MODEL, D_MODEL);
    split_kernel<<<(N_ROWS * D_MODEL) / 1024, 256>>>(src_x, shi, slo);
    ln_split_kernel<<<N_ROWS, 256>>>(x1, ln2_g, ln2_b, ahi, alo);
    tc_gemm<false, false, false><<<gD, 256, TC_SMEM>>>(ahi, alo, whi + CQ_OFF, wlo + CQ_OFF, Bv[4], nullptr, q, nullptr, nullptr, N_ROWS, D_MODEL, D_MODEL);
    tc_gemm<false, false, false><<<gD, 256, TC_SMEM>>>(shi, slo, whi + CK_OFF, wlo + CK_OFF, Bv[5], nullptr, k, nullptr, nullptr, N_ROWS, D_MODEL, D_MODEL);
    tc_gemm<false, false, false><<<gD, 256, TC_SMEM>>>(shi, slo, whi + CV_OFF, wlo + CV_OFF, Bv[6], nullptr, v, nullptr, nullptr, N_ROWS, D_MODEL, D_MODEL);
    attn_kernel<<<gAtt, 256, ATTN_SMEM>>>(q, k, v, ahi, alo, 0);
    tc_gemm<false, true, false><<<gD, 256, TC_SMEM>>>(ahi, alo, whi + CO_OFF, wlo + CO_OFF, Bv[7], x1, x2, nullptr, nullptr, N_ROWS, D_MODEL, D_MODEL);

    // ---- FFN block ----
    {
        dim3 g1(DFF_ / 32, D_MODEL / 32);
        tsplit_kernel<<<g1, 256>>>(ff_w1, whi + W1_OFF, wlo + W1_OFF, D_MODEL, DFF_);
        dim3 g2(D_MODEL / 32, DFF_ / 32);
        tsplit_kernel<<<g2, 256>>>(ff_w2, whi + W2_OFF, wlo + W2_OFF, DFF_, D_MODEL);
    }
    ln_split_kernel<<<N_ROWS, 256>>>(x2, ln3_g, ln3_b, ahi, alo);
    tc_gemm<true, false, true><<<gF1, 256, TC_SMEM>>>(ahi, alo, whi + W1_OFF, wlo + W1_OFF, ff_b1, nullptr, nullptr, fhi, flo, N_ROWS, DFF_, D_MODEL);
    tc_gemm<false, true, false><<<gD, 256, TC_SMEM>>>(fhi, flo, whi + W2_OFF, wlo + W2_OFF, ff_b2, x2, out, nullptr, nullptr, N_ROWS, D_MODEL, DFF_);
}